// round 12
// baseline (speedup 1.0000x reference)
#include <cuda_runtime.h>
#include <cuda_bf16.h>
#include <math.h>

// Problem constants (dataset-fixed; scratch capacity)
#define N_NODES 50000
#define DIM     64
#define N_EDGES 1600000
#define SCAN_B  512

// ---------------------------------------------------------------------------
// Scratch (device globals — no allocation allowed; zero-init at module load)
// ---------------------------------------------------------------------------
__device__ float4 g_acc4[N_NODES * (DIM / 4)];   // 12.8 MB accumulator
__device__ float  g_p[N_NODES];                  // feat[i] . lin_w[0:64]
__device__ float  g_q[N_NODES];                  // feat[i] . lin_w[64:128]
__device__ int    g_deg[N_NODES];                // in-degree (must be 0 at entry;
                                                 // zeroed by build_kernel for replays)
__device__ int    g_offsets[N_NODES + 1];        // CSR row offsets (by dst)
__device__ int    g_cursor[N_NODES];             // bump cursors for build
__device__ int    g_csr_src[N_EDGES];            // src ids sorted by dst (6.4 MB)

// ---------------------------------------------------------------------------
// Kernel 1: fused per-node pq dots + in-degree histogram (grid split).
// ---------------------------------------------------------------------------
__global__ void __launch_bounds__(256)
pq_hist_kernel(const float* __restrict__ feat,
               const float* __restrict__ lin_w,
               const int* __restrict__ edst,
               int n_nodes, int n_edges, int pq_blocks) {
    if ((int)blockIdx.x < pq_blocks) {
        int wid  = (blockIdx.x * blockDim.x + threadIdx.x) >> 5;
        int lane = threadIdx.x & 31;
        if (wid >= n_nodes) return;

        float f0 = feat[wid * DIM + lane];
        float f1 = feat[wid * DIM + lane + 32];
        float pv = f0 * lin_w[lane]      + f1 * lin_w[lane + 32];
        float qv = f0 * lin_w[64 + lane] + f1 * lin_w[96 + lane];

        #pragma unroll
        for (int off = 16; off > 0; off >>= 1) {
            pv += __shfl_xor_sync(0xffffffffu, pv, off);
            qv += __shfl_xor_sync(0xffffffffu, qv, off);
        }
        if (lane == 0) {
            g_p[wid] = pv;
            g_q[wid] = qv;
        }
    } else {
        int e = (blockIdx.x - pq_blocks) * blockDim.x + threadIdx.x;
        if (e < n_edges) atomicAdd(&g_deg[edst[e]], 1);
    }
}

// ---------------------------------------------------------------------------
// Kernel 2: single-launch exclusive scan (redundant prefix per block).
// ---------------------------------------------------------------------------
__global__ void __launch_bounds__(SCAN_B)
fullscan_kernel(int n_nodes, int n_edges) {
    __shared__ int tile[SCAN_B];
    __shared__ int wsum[SCAN_B / 32];
    __shared__ int sbase;

    int t     = threadIdx.x;
    int lane  = t & 31;
    int wid   = t >> 5;
    int start = blockIdx.x * SCAN_B;

    int part = 0;
    for (int i = t; i < start; i += SCAN_B) part += g_deg[i];
    #pragma unroll
    for (int off = 16; off > 0; off >>= 1)
        part += __shfl_xor_sync(0xffffffffu, part, off);
    if (lane == 0) wsum[wid] = part;
    __syncthreads();
    if (t == 0) {
        int s = 0;
        #pragma unroll
        for (int w = 0; w < SCAN_B / 32; w++) s += wsum[w];
        sbase = s;
    }

    int v = (start + t < n_nodes) ? g_deg[start + t] : 0;
    tile[t] = v;
    __syncthreads();
    #pragma unroll
    for (int off = 1; off < SCAN_B; off <<= 1) {
        int tv = (t >= off) ? tile[t - off] : 0;
        __syncthreads();
        tile[t] += tv;
        __syncthreads();
    }
    int off_val = sbase + tile[t] - v;   // exclusive
    if (start + t < n_nodes) {
        g_offsets[start + t] = off_val;
        g_cursor[start + t]  = off_val;
    }
    if (start + t == 0) g_offsets[n_nodes] = n_edges;
}

// ---------------------------------------------------------------------------
// Kernel 3: CSR build (+ re-zero g_deg for next graph replay).
// ---------------------------------------------------------------------------
__global__ void __launch_bounds__(256)
build_kernel(const int* __restrict__ esrc, const int* __restrict__ edst,
             int n_edges, int n_nodes) {
    int e = blockIdx.x * blockDim.x + threadIdx.x;
    if (e < n_nodes) g_deg[e] = 0;     // n_edges >= n_nodes here
    if (e < n_edges) {
        int d = edst[e];
        int pos = atomicAdd(&g_cursor[d], 1);
        g_csr_src[pos] = esrc[e];
    }
}

// ---------------------------------------------------------------------------
// Kernel 4: gather — half-warp float4 layout, 2 edges per inner iteration.
//   Lane l: half = l>>4, chunk c = l&15 (owns float4 c of the 64-dim row).
//   Half h processes edges 2j+h; partials combined via shfl_xor(16) at end.
// ---------------------------------------------------------------------------
__global__ void __launch_bounds__(256)
gather_kernel(const float4* __restrict__ feat4,
              const float* __restrict__ lin_b,
              int n_nodes) {
    int warp  = (blockIdx.x * blockDim.x + threadIdx.x) >> 5;
    int lane  = threadIdx.x & 31;
    int half  = lane >> 4;
    int c     = lane & 15;
    int nwarp = (gridDim.x * blockDim.x) >> 5;
    float b = lin_b[0];

    for (int i = warp; i < n_nodes; i += nwarp) {
        int off = g_offsets[i];
        int end = g_offsets[i + 1];
        float qd = g_q[i] + b;
        float4 acc = make_float4(0.f, 0.f, 0.f, 0.f);

        for (int base = off; base < end; base += 32) {
            int cnt = end - base;
            if (cnt > 32) cnt = 32;
            int  e_ok = (lane < cnt);
            int  s_l  = e_ok ? g_csr_src[base + lane] : 0;
            float p_l = e_ok ? g_p[s_l] : 0.f;
            float x   = fmaxf(p_l + qd, 0.f);
            float a_l = 1.f / (1.f + __expf(-x));

            if (cnt == 32) {
                #pragma unroll 4
                for (int j = 0; j < 16; j++) {
                    int   srcl = 2 * j + half;
                    int   s = __shfl_sync(0xffffffffu, s_l, srcl);
                    float a = __shfl_sync(0xffffffffu, a_l, srcl);
                    float4 v = feat4[s * 16 + c];
                    acc.x = fmaf(a, v.x, acc.x);
                    acc.y = fmaf(a, v.y, acc.y);
                    acc.z = fmaf(a, v.z, acc.z);
                    acc.w = fmaf(a, v.w, acc.w);
                }
            } else {
                int npair = (cnt + 1) >> 1;
                for (int j = 0; j < npair; j++) {
                    int   eidx = 2 * j + half;
                    int   s = __shfl_sync(0xffffffffu, s_l, eidx);
                    float a = __shfl_sync(0xffffffffu, a_l, eidx);
                    if (eidx < cnt) {
                        float4 v = feat4[s * 16 + c];
                        acc.x = fmaf(a, v.x, acc.x);
                        acc.y = fmaf(a, v.y, acc.y);
                        acc.z = fmaf(a, v.z, acc.z);
                        acc.w = fmaf(a, v.w, acc.w);
                    }
                }
            }
        }
        // combine half-warp partials (chunk c lives in lanes c and c+16)
        acc.x += __shfl_xor_sync(0xffffffffu, acc.x, 16);
        acc.y += __shfl_xor_sync(0xffffffffu, acc.y, 16);
        acc.z += __shfl_xor_sync(0xffffffffu, acc.z, 16);
        acc.w += __shfl_xor_sync(0xffffffffu, acc.w, 16);
        if (half == 0) g_acc4[i * 16 + c] = acc;
    }
}

// ---------------------------------------------------------------------------
// Kernel 5: finalize with weight columns in registers.
// ---------------------------------------------------------------------------
__global__ void __launch_bounds__(128)
finalize_kernel(const float* __restrict__ feat,
                const float* __restrict__ norm,
                const float* __restrict__ W_rel,
                const float* __restrict__ loop_w,
                const float* __restrict__ evolve_w,
                float* __restrict__ out,
                int n_nodes) {
    __shared__ float4 sF4[2][DIM / 4];
    __shared__ float4 sA4[2][DIM / 4];

    int j  = threadIdx.x & 63;
    int gr = threadIdx.x >> 6;

    float wr[DIM], wl[DIM];
    #pragma unroll
    for (int k = 0; k < DIM; k++) wr[k] = W_rel[k * DIM + j];
    #pragma unroll
    for (int k = 0; k < DIM; k++) wl[k] = loop_w[k * DIM + j];

    const float* accf = (const float*)g_acc4;
    int gstride = gridDim.x * 2;
    int g0 = blockIdx.x * 2 + gr;
    int iters = (n_nodes + gstride - 1) / gstride;

    for (int it = 0; it < iters; it++) {
        int i = g0 + it * gstride;
        __syncthreads();
        if (i < n_nodes) {
            ((float*)sF4[gr])[j] = feat[i * DIM + j];
            ((float*)sA4[gr])[j] = accf[i * DIM + j];
        }
        __syncthreads();
        if (i < n_nodes) {
            bool has = (g_offsets[i + 1] > g_offsets[i]);
            float accv = 0.f, loopv = 0.f;
            if (has) {
                #pragma unroll
                for (int kk = 0; kk < DIM / 4; kk++) {
                    float4 a4 = sA4[gr][kk];
                    float4 f4 = sF4[gr][kk];
                    accv  = fmaf(a4.x, wr[4 * kk + 0], accv);
                    accv  = fmaf(a4.y, wr[4 * kk + 1], accv);
                    accv  = fmaf(a4.z, wr[4 * kk + 2], accv);
                    accv  = fmaf(a4.w, wr[4 * kk + 3], accv);
                    loopv = fmaf(f4.x, wl[4 * kk + 0], loopv);
                    loopv = fmaf(f4.y, wl[4 * kk + 1], loopv);
                    loopv = fmaf(f4.z, wl[4 * kk + 2], loopv);
                    loopv = fmaf(f4.w, wl[4 * kk + 3], loopv);
                }
            } else {
                const float* sFp = (const float*)sF4[gr];
                #pragma unroll 8
                for (int k = 0; k < DIM; k++)
                    loopv = fmaf(sFp[k], evolve_w[k * DIM + j], loopv);
            }
            float nrm = norm[i];
            float nf = has ? accv * nrm : ((const float*)sF4[gr])[j] * nrm;
            out[i * DIM + j] = tanhf(nf + loopv);
        }
    }
}

// ---------------------------------------------------------------------------
// Launch
// Inputs (metadata order): feat, norm, edge_src, edge_dst, etype,
//                          W_rel, lin_w, lin_b, loop_w, evolve_loop_w
// ---------------------------------------------------------------------------
extern "C" void kernel_launch(void* const* d_in, const int* in_sizes, int n_in,
                              void* d_out, int out_size) {
    const float* feat     = (const float*)d_in[0];
    const float* norm     = (const float*)d_in[1];
    const int*   edge_src = (const int*)  d_in[2];
    const int*   edge_dst = (const int*)  d_in[3];
    // d_in[4] = etype: unused (same W_rel for every type)
    const float* W_rel    = (const float*)d_in[5];
    const float* lin_w    = (const float*)d_in[6];
    const float* lin_b    = (const float*)d_in[7];
    const float* loop_w   = (const float*)d_in[8];
    const float* evolve_w = (const float*)d_in[9];
    float*       out      = (float*)d_out;

    int n_nodes = in_sizes[1];
    int n_edges = in_sizes[2];
    if (n_nodes > N_NODES) n_nodes = N_NODES;
    if (n_edges > N_EDGES) n_edges = N_EDGES;

    int pq_blocks   = (n_nodes * 32 + 255) / 256;
    int hist_blocks = (n_edges + 255) / 256;
    int scan_blocks = (n_nodes + SCAN_B - 1) / SCAN_B;

    // 1) fused pq + histogram
    pq_hist_kernel<<<pq_blocks + hist_blocks, 256>>>(
        feat, lin_w, edge_dst, n_nodes, n_edges, pq_blocks);
    // 2) one-shot scan -> offsets + cursor
    fullscan_kernel<<<scan_blocks, SCAN_B>>>(n_nodes, n_edges);
    // 3) CSR build (+ re-zero deg for next replay)
    build_kernel<<<hist_blocks, 256>>>(edge_src, edge_dst, n_edges, n_nodes);
    // 4) gather: half-warp float4, warp per node, grid-stride
    gather_kernel<<<1216, 256>>>((const float4*)feat, lin_b, n_nodes);
    // 5) finalize: W in registers
    finalize_kernel<<<456, 128>>>(feat, norm, W_rel, loop_w, evolve_w, out, n_nodes);
}